// round 8
// baseline (speedup 1.0000x reference)
#include <cuda_runtime.h>
#include <cuda_bf16.h>
#include <math.h>

typedef unsigned long long ull;

// Problem constants
#define BB   256          // batch
#define TT   512          // seq len
#define HH   256          // hidden
#define GG   1024         // 4*H gates
#define CC   128          // classes
#define MM   (BB*TT)      // 131072 rows for input GEMMs

// ---------------- scratch (device globals; no allocs allowed) ----------------
__device__ float g_GX[(size_t)MM * GG];      // 512 MB  pregates, layout [t][b][gate]
__device__ float g_HBUF[(size_t)MM * HH];    // 128 MB  layer-0 hidden states
__device__ float g_H0[BB * HH];
__device__ float g_H1[BB * HH];
__device__ unsigned int g_bar;               // grid barrier counter

// ---------------- packed f32x2 helpers (Blackwell FFMA2 path) ----------------
__device__ __forceinline__ ull pack2(float x, float y) {
    ull r;
    asm("mov.b64 %0, {%1, %2};" : "=l"(r) : "f"(x), "f"(y));
    return r;
}
__device__ __forceinline__ float2 unpack2(ull v) {
    float2 r;
    asm("mov.b64 {%0, %1}, %2;" : "=f"(r.x), "=f"(r.y) : "l"(v));
    return r;
}
__device__ __forceinline__ ull ffma2x(ull a, ull b, ull c) {
    ull d;
    asm("fma.rn.f32x2 %0, %1, %2, %3;" : "=l"(d) : "l"(a), "l"(b), "l"(c));
    return d;
}

// fast activations (error ~1e-6, well inside 1e-3 budget)
__device__ __forceinline__ float fsigm(float x) {
    float e = __expf(-x);
    return __fdividef(1.0f, 1.0f + e);
}
__device__ __forceinline__ float ftanh(float x) {
    float e = __expf(2.0f * x);           // overflow -> inf -> result 1 (correct)
    return 1.0f - __fdividef(2.0f, e + 1.0f);
}

// ---------------- big GEMM:  GX[t][b][n] = sum_k A[m,k]*W[n,k] + b1[n] + b2[n]
// A: [MM,256] row-major (x, or g_HBUF), m = b*TT + t. W: [1024,256] row-major.
// Tiles: BM=128, BN=64, BK=16, 256 threads, thread tile 8x4 (4 m-pairs x 4 n).
__global__ void __launch_bounds__(256) gemm_gx(const float* __restrict__ Aext,
                                               int useExt,
                                               const float* __restrict__ W,
                                               const float* __restrict__ b1,
                                               const float* __restrict__ b2) {
    __shared__ __align__(16) float As[16][128];
    __shared__ __align__(16) float Bs[16][64];

    const float* __restrict__ A = useExt ? Aext : g_HBUF;
    float* __restrict__ Cout = g_GX;

    const int tid = threadIdx.x;
    const int ty = tid >> 4;          // 0..15  (m group of 8)
    const int tx = tid & 15;          // 0..15  (n group of 4)
    const int bm0 = blockIdx.y * 128;
    const int bn0 = blockIdx.x * 64;

    ull acc[4][4];
    #pragma unroll
    for (int i = 0; i < 4; i++)
        #pragma unroll
        for (int j = 0; j < 4; j++) acc[i][j] = 0ull;

    for (int k0 = 0; k0 < 256; k0 += 16) {
        #pragma unroll
        for (int i = 0; i < 2; i++) {
            int s = tid + i * 256;          // 0..511
            int row = s >> 2;               // 0..127
            int kg = (s & 3) * 4;           // 0,4,8,12
            float4 v = *(const float4*)&A[(size_t)(bm0 + row) * 256 + k0 + kg];
            As[kg + 0][row] = v.x; As[kg + 1][row] = v.y;
            As[kg + 2][row] = v.z; As[kg + 3][row] = v.w;
        }
        {
            int row = tid >> 2;             // 0..63
            int kg = (tid & 3) * 4;
            float4 v = *(const float4*)&W[(size_t)(bn0 + row) * 256 + k0 + kg];
            Bs[kg + 0][row] = v.x; Bs[kg + 1][row] = v.y;
            Bs[kg + 2][row] = v.z; Bs[kg + 3][row] = v.w;
        }
        __syncthreads();
        #pragma unroll
        for (int k = 0; k < 16; k++) {
            const ull* ap = (const ull*)&As[k][ty * 8];
            ull a0 = ap[0], a1 = ap[1], a2 = ap[2], a3 = ap[3];
            float4 bv = *(const float4*)&Bs[k][tx * 4];
            ull bb0 = pack2(bv.x, bv.x);
            ull bb1 = pack2(bv.y, bv.y);
            ull bb2 = pack2(bv.z, bv.z);
            ull bb3 = pack2(bv.w, bv.w);
            acc[0][0] = ffma2x(a0, bb0, acc[0][0]);
            acc[1][0] = ffma2x(a1, bb0, acc[1][0]);
            acc[2][0] = ffma2x(a2, bb0, acc[2][0]);
            acc[3][0] = ffma2x(a3, bb0, acc[3][0]);
            acc[0][1] = ffma2x(a0, bb1, acc[0][1]);
            acc[1][1] = ffma2x(a1, bb1, acc[1][1]);
            acc[2][1] = ffma2x(a2, bb1, acc[2][1]);
            acc[3][1] = ffma2x(a3, bb1, acc[3][1]);
            acc[0][2] = ffma2x(a0, bb2, acc[0][2]);
            acc[1][2] = ffma2x(a1, bb2, acc[1][2]);
            acc[2][2] = ffma2x(a2, bb2, acc[2][2]);
            acc[3][2] = ffma2x(a3, bb2, acc[3][2]);
            acc[0][3] = ffma2x(a0, bb3, acc[0][3]);
            acc[1][3] = ffma2x(a1, bb3, acc[1][3]);
            acc[2][3] = ffma2x(a2, bb3, acc[2][3]);
            acc[3][3] = ffma2x(a3, bb3, acc[3][3]);
        }
        __syncthreads();
    }

    float4 b1v = *(const float4*)&b1[bn0 + tx * 4];
    float4 b2v = *(const float4*)&b2[bn0 + tx * 4];
    float4 bias = make_float4(b1v.x + b2v.x, b1v.y + b2v.y,
                              b1v.z + b2v.z, b1v.w + b2v.w);
    #pragma unroll
    for (int i = 0; i < 4; i++) {
        float2 q0 = unpack2(acc[i][0]);
        float2 q1 = unpack2(acc[i][1]);
        float2 q2 = unpack2(acc[i][2]);
        float2 q3 = unpack2(acc[i][3]);
        size_t m0 = (size_t)(bm0 + ty * 8 + 2 * i);
        size_t m1 = m0 + 1;
        // permuted output: row = t*BB + b, with m = b*TT + t
        size_t r0 = (m0 & (TT - 1)) * BB + (m0 >> 9);
        size_t r1 = (m1 & (TT - 1)) * BB + (m1 >> 9);
        float4 v0 = make_float4(q0.x + bias.x, q1.x + bias.y, q2.x + bias.z, q3.x + bias.w);
        float4 v1 = make_float4(q0.y + bias.x, q1.y + bias.y, q2.y + bias.z, q3.y + bias.w);
        *(float4*)&Cout[r0 * GG + bn0 + tx * 4] = v0;
        *(float4*)&Cout[r1 * GG + bn0 + tx * 4] = v1;
    }
}

// ---------------- barrier reset ----------------
__global__ void reset_bar() { g_bar = 0u; }

// ---------------- persistent recurrence kernel -------------------------------
// Grid (8,16) = 128 CTAs (1/SM), 512 threads = 16 warps (4/SMSP).
// CTA tile: 16 batch rows x 32 h-cols x 4 gates. Warp = 8 rows x 4 cols,
// thread = 1 row x 1 col x 4 gates (2 f32x2 accs: (i,f) and (g,o)).
// Per k per warp: LDS.64 dup-h (64B unique) + LDS.128 gate-weights (64B
// unique) + 2 FFMA2 -> 4 inst, 128B crossbar. All warps read DISJOINT
// weight cols -> no cross-warp redundancy: xbar = fma = issue = 4096 cyc.
__global__ void __launch_bounds__(512, 1) lstm_persist(const float* __restrict__ whh,
                                                       int writeHbuf) {
    extern __shared__ float smx[];
    float* sW = smx;                       // [256][32 cols][4 gates] floats
    ull*   sH = (ull*)(smx + 256 * 128);   // [256][16 rows] dup (h,h)

    const int tid  = threadIdx.x;
    const int w    = tid >> 5;            // warp 0..15
    const int lane = tid & 31;
    const int cq   = w & 7;               // col quad 0..7
    const int rh   = w >> 3;              // row half 0..1
    const int r    = rh * 8 + (lane >> 2);  // CTA-local row 0..15
    const int c    = cq * 4 + (lane & 3);   // CTA-local col 0..31
    const int c0   = blockIdx.x * 32;     // h-col group
    const int bm   = blockIdx.y * 16;     // batch-row group
    const int row  = bm + r;
    const int col  = c0 + c;

    // one-time weight stage: sW[k*128 + c*4 + g], lanes -> contiguous smem
    {
        int lr = tid & 127;               // c*4 + g
        int half = tid >> 7;              // 0..3 (64 k each)
        int cc = lr >> 2, g = lr & 3;
        const float* wrow = &whh[(size_t)(g * HH + c0 + cc) * HH + half * 64];
        #pragma unroll
        for (int j = 0; j < 16; j++) {
            float4 v = *(const float4*)&wrow[j * 4];
            int kk = half * 64 + j * 4;
            sW[(kk + 0) * 128 + lr] = v.x;
            sW[(kk + 1) * 128 + lr] = v.y;
            sW[(kk + 2) * 128 + lr] = v.z;
            sW[(kk + 3) * 128 + lr] = v.w;
        }
    }
    __syncthreads();

    float creg = 0.f;

    // t=0 pregate prefetch (GX layout [t][b][gate], t=0)
    float pi, pf, pg, po;
    {
        size_t base = (size_t)row * GG + col;
        pi = g_GX[base];
        pf = g_GX[base + 256];
        pg = g_GX[base + 512];
        po = g_GX[base + 768];
    }

    const int sr  = tid & 15;             // staging row
    const int skc = tid >> 4;             // staging k-chunk 0..31 (8 k each)

    for (int t = 0; t < TT; t++) {
        const float* __restrict__ hin  = (t & 1) ? g_H1 : g_H0;
        float* __restrict__       hout = (t & 1) ? g_H0 : g_H1;

        ull aif = 0, ago = 0;

        if (t > 0) {   // h == 0 at t=0, recurrent term vanishes
            // stage hin (16 rows x 256 k) duplicated: sH[k*16 + row]
            {
                const float* hrow = &hin[(bm + sr) * HH + skc * 8];
                float4 v0 = *(const float4*)&hrow[0];
                float4 v1 = *(const float4*)&hrow[4];
                int kb = skc * 8;
                sH[(kb + 0) * 16 + sr] = pack2(v0.x, v0.x);
                sH[(kb + 1) * 16 + sr] = pack2(v0.y, v0.y);
                sH[(kb + 2) * 16 + sr] = pack2(v0.z, v0.z);
                sH[(kb + 3) * 16 + sr] = pack2(v0.w, v0.w);
                sH[(kb + 4) * 16 + sr] = pack2(v1.x, v1.x);
                sH[(kb + 5) * 16 + sr] = pack2(v1.y, v1.y);
                sH[(kb + 6) * 16 + sr] = pack2(v1.z, v1.z);
                sH[(kb + 7) * 16 + sr] = pack2(v1.w, v1.w);
            }
            __syncthreads();

            const ull* hp = sH + r;                               // + k*16
            const ulonglong2* wp = (const ulonglong2*)sW + c;     // + k*32
            #pragma unroll 16
            for (int k = 0; k < 256; k++) {
                ull hv = hp[k * 16];             // (h,h) broadcast
                ulonglong2 wv = wp[k * 32];      // (wi,wf),(wg,wo)
                aif = ffma2x(hv, wv.x, aif);
                ago = ffma2x(hv, wv.y, ago);
            }
            __syncthreads();   // sH re-staged next step
        }

        float2 fif = unpack2(aif), fgo = unpack2(ago);
        {
            float si = fsigm(fif.x + pi);
            float sf = fsigm(fif.y + pf);
            float tg = ftanh(fgo.x + pg);
            float so = fsigm(fgo.y + po);
            creg = sf * creg + si * tg;
            float h = so * ftanh(creg);
            hout[row * HH + col] = h;
            if (writeHbuf) g_HBUF[((size_t)row * TT + t) * HH + col] = h;
        }

        if (t < TT - 1) {
            __syncthreads();                       // all h stores issued
            if (tid == 0) {
                __threadfence();                   // release h to GPU scope
                atomicAdd(&g_bar, 1u);
            }
            // prefetch next step's pregates while peers arrive
            {
                size_t base = ((size_t)(t + 1) * BB + row) * GG + col;
                pi = g_GX[base];
                pf = g_GX[base + 256];
                pg = g_GX[base + 512];
                po = g_GX[base + 768];
            }
            if (tid == 0) {
                unsigned target = (unsigned)(t + 1) * 128u;
                unsigned v;
                do {
                    asm volatile("ld.global.acquire.gpu.u32 %0, [%1];"
                                 : "=r"(v) : "l"(&g_bar));
                } while (v < target);
            }
            __syncthreads();
        }
    }
}

// ---------------- FC + log_softmax ------------------------------------------
__global__ void __launch_bounds__(128) fc_kernel(const float* __restrict__ wfc,
                                                 const float* __restrict__ bfc,
                                                 float* __restrict__ out) {
    const int b = blockIdx.x;
    const int tid = threadIdx.x;  // 128 = one class per thread
    __shared__ float h[256];
    // t = TT-1 = 511 (odd) -> final hout = g_H0
    h[tid] = g_H0[b * HH + tid];
    h[tid + 128] = g_H0[b * HH + tid + 128];
    __syncthreads();

    float acc = bfc[tid];
    const float* wp = wfc + (size_t)tid * HH;
    #pragma unroll 8
    for (int k = 0; k < 256; k++) acc += h[k] * wp[k];

    float m = acc;
    #pragma unroll
    for (int o = 16; o > 0; o >>= 1)
        m = fmaxf(m, __shfl_xor_sync(0xffffffffu, m, o));
    __shared__ float smax[4], ssum[4];
    int wid = tid >> 5, lane = tid & 31;
    if (lane == 0) smax[wid] = m;
    __syncthreads();
    m = fmaxf(fmaxf(smax[0], smax[1]), fmaxf(smax[2], smax[3]));

    float e = expf(acc - m);
    float s = e;
    #pragma unroll
    for (int o = 16; o > 0; o >>= 1)
        s += __shfl_xor_sync(0xffffffffu, s, o);
    if (lane == 0) ssum[wid] = s;
    __syncthreads();
    s = ssum[0] + ssum[1] + ssum[2] + ssum[3];

    out[b * CC + tid] = acc - m - logf(s);
}

// ---------------- launch ------------------------------------------------------
extern "C" void kernel_launch(void* const* d_in, const int* in_sizes, int n_in,
                              void* d_out, int out_size) {
    const float* x    = (const float*)d_in[0];
    const float* wih0 = (const float*)d_in[1];
    const float* whh0 = (const float*)d_in[2];
    const float* bih0 = (const float*)d_in[3];
    const float* bhh0 = (const float*)d_in[4];
    const float* wih1 = (const float*)d_in[5];
    const float* whh1 = (const float*)d_in[6];
    const float* bih1 = (const float*)d_in[7];
    const float* bhh1 = (const float*)d_in[8];
    const float* wfc  = (const float*)d_in[9];
    const float* bfc  = (const float*)d_in[10];
    float* out = (float*)d_out;

    const int persist_smem = (256 * 128) * 4 + (256 * 16) * 8;   // 160 KB
    cudaFuncSetAttribute(lstm_persist,
                         cudaFuncAttributeMaxDynamicSharedMemorySize,
                         persist_smem);

    dim3 gemm_grid(16, 1024);   // N/64, M/128
    dim3 step_grid(8, 16);      // col-groups x row-groups = 128 CTAs

    // Layer 0
    gemm_gx<<<gemm_grid, 256>>>(x, 1, wih0, bih0, bhh0);
    reset_bar<<<1, 1>>>();
    lstm_persist<<<step_grid, 512, persist_smem>>>(whh0, 1);

    // Layer 1
    gemm_gx<<<gemm_grid, 256>>>(nullptr, 0, wih1, bih1, bhh1);
    reset_bar<<<1, 1>>>();
    lstm_persist<<<step_grid, 512, persist_smem>>>(whh1, 0);

    // Head
    fc_kernel<<<256, 128>>>(wfc, bfc, out);
}

// round 9
// speedup vs baseline: 1.2101x; 1.2101x over previous
#include <cuda_runtime.h>
#include <cuda_bf16.h>
#include <math.h>

typedef unsigned long long ull;

// Problem constants
#define BB   256          // batch
#define TT   512          // seq len
#define HH   256          // hidden
#define GG   1024         // 4*H gates
#define CC   128          // classes
#define MM   (BB*TT)      // 131072 rows for input GEMMs

// ---------------- scratch (device globals; no allocs allowed) ----------------
__device__ float g_GX[(size_t)MM * GG];      // 512 MB  pregates, layout [b][t][gate]
__device__ float g_HBUF[(size_t)MM * HH];    // 128 MB  layer-0 hidden states
__device__ float g_H0[BB * HH];
__device__ float g_H1[BB * HH];
// mailbox barrier: one 128B line per CTA, store/load only (no atomics)
__device__ int g_arrive[128 * 32];
__device__ int g_release[128 * 32];

// ---------------- packed f32x2 helpers (Blackwell FFMA2 path) ----------------
__device__ __forceinline__ ull pack2(float x, float y) {
    ull r;
    asm("mov.b64 %0, {%1, %2};" : "=l"(r) : "f"(x), "f"(y));
    return r;
}
__device__ __forceinline__ float2 unpack2(ull v) {
    float2 r;
    asm("mov.b64 {%0, %1}, %2;" : "=f"(r.x), "=f"(r.y) : "l"(v));
    return r;
}
__device__ __forceinline__ ull ffma2x(ull a, ull b, ull c) {
    ull d;
    asm("fma.rn.f32x2 %0, %1, %2, %3;" : "=l"(d) : "l"(a), "l"(b), "l"(c));
    return d;
}

// fast activations (error ~1e-6, well inside 1e-3 budget)
__device__ __forceinline__ float fsigm(float x) {
    float e = __expf(-x);
    return __fdividef(1.0f, 1.0f + e);
}
__device__ __forceinline__ float ftanh(float x) {
    float e = __expf(2.0f * x);           // overflow -> inf -> result 1 (correct)
    return 1.0f - __fdividef(2.0f, e + 1.0f);
}

__device__ __forceinline__ void st_release(int* p, int v) {
    asm volatile("st.global.release.gpu.s32 [%0], %1;" :: "l"(p), "r"(v) : "memory");
}
__device__ __forceinline__ int ld_acquire(const int* p) {
    int v;
    asm volatile("ld.global.acquire.gpu.s32 %0, [%1];" : "=r"(v) : "l"(p) : "memory");
    return v;
}

// ---------------- big GEMM:  Cout[m,n] = sum_k A[m,k]*W[n,k] + b1[n] + b2[n] --
// A: [MM,256] row-major (x, or g_HBUF), W: [1024,256] row-major.
// Tiles: BM=128, BN=64, BK=16, 256 threads, thread tile 8x4 (4 m-pairs x 4 n).
// Double-buffered smem: LDG of tile k+1 overlaps compute of tile k.
__global__ void __launch_bounds__(256) gemm_gx(const float* __restrict__ Aext,
                                               int useExt,
                                               const float* __restrict__ W,
                                               const float* __restrict__ b1,
                                               const float* __restrict__ b2) {
    __shared__ __align__(16) float As[2][16][128];
    __shared__ __align__(16) float Bs[2][16][64];

    const float* __restrict__ A = useExt ? Aext : g_HBUF;
    float* __restrict__ Cout = g_GX;

    const int tid = threadIdx.x;
    const int ty = tid >> 4;          // 0..15  (m group of 8)
    const int tx = tid & 15;          // 0..15  (n group of 4)
    const int bm0 = blockIdx.y * 128;
    const int bn0 = blockIdx.x * 64;

    // loader indices
    const int a_row0 = tid >> 2;              // 0..63   (i=0 slice)
    const int a_kg   = (tid & 3) * 4;
    const int b_row  = tid >> 2;              // 0..63
    const int b_kg   = (tid & 3) * 4;

    ull acc[4][4];
    #pragma unroll
    for (int i = 0; i < 4; i++)
        #pragma unroll
        for (int j = 0; j < 4; j++) acc[i][j] = 0ull;

    // preload tile k0=0 into buffer 0
    {
        #pragma unroll
        for (int i = 0; i < 2; i++) {
            int row = a_row0 + i * 64;
            float4 v = *(const float4*)&A[(size_t)(bm0 + row) * 256 + a_kg];
            As[0][a_kg + 0][row] = v.x; As[0][a_kg + 1][row] = v.y;
            As[0][a_kg + 2][row] = v.z; As[0][a_kg + 3][row] = v.w;
        }
        float4 v = *(const float4*)&W[(size_t)(bn0 + b_row) * 256 + b_kg];
        Bs[0][b_kg + 0][b_row] = v.x; Bs[0][b_kg + 1][b_row] = v.y;
        Bs[0][b_kg + 2][b_row] = v.z; Bs[0][b_kg + 3][b_row] = v.w;
    }
    __syncthreads();

    int buf = 0;
    for (int k0 = 0; k0 < 256; k0 += 16) {
        // prefetch next tile into registers (overlaps compute)
        float4 pa0, pa1, pb;
        const bool more = (k0 + 16) < 256;
        if (more) {
            pa0 = *(const float4*)&A[(size_t)(bm0 + a_row0) * 256 + k0 + 16 + a_kg];
            pa1 = *(const float4*)&A[(size_t)(bm0 + a_row0 + 64) * 256 + k0 + 16 + a_kg];
            pb  = *(const float4*)&W[(size_t)(bn0 + b_row) * 256 + k0 + 16 + b_kg];
        }

        #pragma unroll
        for (int k = 0; k < 16; k++) {
            const ull* ap = (const ull*)&As[buf][k][ty * 8];
            ull a0 = ap[0], a1 = ap[1], a2 = ap[2], a3 = ap[3];
            float4 bv = *(const float4*)&Bs[buf][k][tx * 4];
            ull bb0 = pack2(bv.x, bv.x);
            ull bb1 = pack2(bv.y, bv.y);
            ull bb2 = pack2(bv.z, bv.z);
            ull bb3 = pack2(bv.w, bv.w);
            acc[0][0] = ffma2x(a0, bb0, acc[0][0]);
            acc[1][0] = ffma2x(a1, bb0, acc[1][0]);
            acc[2][0] = ffma2x(a2, bb0, acc[2][0]);
            acc[3][0] = ffma2x(a3, bb0, acc[3][0]);
            acc[0][1] = ffma2x(a0, bb1, acc[0][1]);
            acc[1][1] = ffma2x(a1, bb1, acc[1][1]);
            acc[2][1] = ffma2x(a2, bb1, acc[2][1]);
            acc[3][1] = ffma2x(a3, bb1, acc[3][1]);
            acc[0][2] = ffma2x(a0, bb2, acc[0][2]);
            acc[1][2] = ffma2x(a1, bb2, acc[1][2]);
            acc[2][2] = ffma2x(a2, bb2, acc[2][2]);
            acc[3][2] = ffma2x(a3, bb2, acc[3][2]);
            acc[0][3] = ffma2x(a0, bb3, acc[0][3]);
            acc[1][3] = ffma2x(a1, bb3, acc[1][3]);
            acc[2][3] = ffma2x(a2, bb3, acc[2][3]);
            acc[3][3] = ffma2x(a3, bb3, acc[3][3]);
        }

        if (more) {
            int nb = buf ^ 1;
            As[nb][a_kg + 0][a_row0] = pa0.x; As[nb][a_kg + 1][a_row0] = pa0.y;
            As[nb][a_kg + 2][a_row0] = pa0.z; As[nb][a_kg + 3][a_row0] = pa0.w;
            As[nb][a_kg + 0][a_row0 + 64] = pa1.x; As[nb][a_kg + 1][a_row0 + 64] = pa1.y;
            As[nb][a_kg + 2][a_row0 + 64] = pa1.z; As[nb][a_kg + 3][a_row0 + 64] = pa1.w;
            Bs[nb][b_kg + 0][b_row] = pb.x; Bs[nb][b_kg + 1][b_row] = pb.y;
            Bs[nb][b_kg + 2][b_row] = pb.z; Bs[nb][b_kg + 3][b_row] = pb.w;
            __syncthreads();
            buf = nb;
        }
    }

    float4 b1v = *(const float4*)&b1[bn0 + tx * 4];
    float4 b2v = *(const float4*)&b2[bn0 + tx * 4];
    float4 bias = make_float4(b1v.x + b2v.x, b1v.y + b2v.y,
                              b1v.z + b2v.z, b1v.w + b2v.w);
    #pragma unroll
    for (int i = 0; i < 4; i++) {
        float2 q0 = unpack2(acc[i][0]);
        float2 q1 = unpack2(acc[i][1]);
        float2 q2 = unpack2(acc[i][2]);
        float2 q3 = unpack2(acc[i][3]);
        size_t r0 = (size_t)(bm0 + ty * 8 + 2 * i);
        float4 v0 = make_float4(q0.x + bias.x, q1.x + bias.y, q2.x + bias.z, q3.x + bias.w);
        float4 v1 = make_float4(q0.y + bias.x, q1.y + bias.y, q2.y + bias.z, q3.y + bias.w);
        *(float4*)&Cout[r0 * GG + bn0 + tx * 4] = v0;
        *(float4*)&Cout[(r0 + 1) * GG + bn0 + tx * 4] = v1;
    }
}

// ---------------- barrier flag reset ----------------
__global__ void reset_flags() {
    int idx = blockIdx.x * blockDim.x + threadIdx.x;   // 8192 threads
    if (idx < 128 * 32) g_arrive[idx] = 0;
    else                g_release[idx - 128 * 32] = 0;
}

// ---------------- persistent recurrence kernel -------------------------------
// 128 blocks x 128 threads (best-measured compute config). Block owns
// 32 batch rows x 16 h-cols (x4 gates). whh slice (64KB) in SMEM for the
// whole sequence; c in registers; h double-buffered in global.
// Cross-CTA sync: contention-free mailbox barrier — per-CTA arrive flags
// (distinct 128B lines), CTA0/warp0 aggregates and fans out per-CTA release
// flags; every line has exactly ONE poller.
__global__ void __launch_bounds__(128, 1) lstm_persist(const float* __restrict__ whh,
                                                       int writeHbuf) {
    extern __shared__ float sm[];
    float* sWs = sm;              // [256][64]   weights, transposed [k][bh*4+g]
    float* sAs = sm + 256 * 64;   // [256][32]   h tile, transposed [k][row]

    const int tid  = threadIdx.x;
    const int bid  = blockIdx.x;
    const int hcol = tid & 15;
    const int rq   = tid >> 4;               // 0..7
    const int c0   = (bid & 15) * 16;        // h-col group
    const int bm   = (bid >> 4) * 32;        // batch-row group
    const int col  = c0 + hcol;

    // one-time weight stage: 64 gate-rows (bh*4+g) x 256 k
    for (int i = tid; i < 64 * 64; i += 128) {
        int lr = i >> 6;              // 0..63 local row
        int kk = (i & 63) * 4;        // k0
        int bh = lr >> 2, g = lr & 3;
        float4 v = *(const float4*)&whh[(size_t)(g * HH + c0 + bh) * HH + kk];
        sWs[(kk + 0) * 64 + lr] = v.x;
        sWs[(kk + 1) * 64 + lr] = v.y;
        sWs[(kk + 2) * 64 + lr] = v.z;
        sWs[(kk + 3) * 64 + lr] = v.w;
    }
    __syncthreads();

    float creg[4] = {0.f, 0.f, 0.f, 0.f};
    int rows[4];
    #pragma unroll
    for (int r = 0; r < 4; r++) rows[r] = bm + rq * 4 + r;

    for (int t = 0; t < TT; t++) {
        const float* __restrict__ hin  = (t & 1) ? g_H1 : g_H0;
        float* __restrict__       hout = (t & 1) ? g_H0 : g_H1;

        // pregate loads (issued early; GX layout [b][t][gate])
        float pg_i[4], pg_f[4], pg_g[4], pg_o[4];
        if (t == 0) {
            #pragma unroll
            for (int r = 0; r < 4; r++) {
                size_t base = ((size_t)rows[r] * TT + t) * GG + col;
                pg_i[r] = g_GX[base];
                pg_f[r] = g_GX[base + 256];
                pg_g[r] = g_GX[base + 512];
                pg_o[r] = g_GX[base + 768];
            }
        } else {
            // loaded during previous barrier window (see below)
            #pragma unroll
            for (int r = 0; r < 4; r++) {
                pg_i[r] = creg[r] == creg[r] ? 0.f : 0.f;  // placeholder, overwritten
            }
        }

        ull ai0 = 0, ai1 = 0, af0 = 0, af1 = 0;
        ull ag0 = 0, ag1 = 0, ao0 = 0, ao1 = 0;

        if (t > 0) {   // h == 0 at t=0, recurrent term vanishes
            // stage hin tile (32 rows x 256 k), transposed
            int r  = tid & 31;
            int kc = tid >> 5;                         // 0..3, 64 k each
            const float* hrow = &hin[(bm + r) * HH + kc * 64];
            #pragma unroll
            for (int j = 0; j < 16; j++) {
                float4 v = *(const float4*)&hrow[j * 4];
                int k0 = kc * 64 + j * 4;
                sAs[(k0 + 0) * 32 + r] = v.x;
                sAs[(k0 + 1) * 32 + r] = v.y;
                sAs[(k0 + 2) * 32 + r] = v.z;
                sAs[(k0 + 3) * 32 + r] = v.w;
            }
            __syncthreads();

            const float* ap = &sAs[rq * 4];
            const float* bp = &sWs[hcol * 4];
            #pragma unroll 8
            for (int k = 0; k < 256; k++) {
                ull a0 = *(const ull*)(ap + k * 32);
                ull a1 = *(const ull*)(ap + k * 32 + 2);
                float4 bv = *(const float4*)(bp + k * 64);   // (i,f,g,o)
                ull bi = pack2(bv.x, bv.x);
                ull bf = pack2(bv.y, bv.y);
                ull bg = pack2(bv.z, bv.z);
                ull bo = pack2(bv.w, bv.w);
                ai0 = ffma2x(a0, bi, ai0); ai1 = ffma2x(a1, bi, ai1);
                af0 = ffma2x(a0, bf, af0); af1 = ffma2x(a1, bf, af1);
                ag0 = ffma2x(a0, bg, ag0); ag1 = ffma2x(a1, bg, ag1);
                ao0 = ffma2x(a0, bo, ao0); ao1 = ffma2x(a1, bo, ao1);
            }
        }

        // pregates for this step (t>0: re-load; L2-hot from barrier-window prefetch)
        if (t > 0) {
            #pragma unroll
            for (int r = 0; r < 4; r++) {
                size_t base = ((size_t)rows[r] * TT + t) * GG + col;
                pg_i[r] = g_GX[base];
                pg_f[r] = g_GX[base + 256];
                pg_g[r] = g_GX[base + 512];
                pg_o[r] = g_GX[base + 768];
            }
        }

        float iv[4], fv[4], gv[4], ov[4];
        {
            float2 p;
            p = unpack2(ai0); iv[0] = p.x; iv[1] = p.y;
            p = unpack2(ai1); iv[2] = p.x; iv[3] = p.y;
            p = unpack2(af0); fv[0] = p.x; fv[1] = p.y;
            p = unpack2(af1); fv[2] = p.x; fv[3] = p.y;
            p = unpack2(ag0); gv[0] = p.x; gv[1] = p.y;
            p = unpack2(ag1); gv[2] = p.x; gv[3] = p.y;
            p = unpack2(ao0); ov[0] = p.x; ov[1] = p.y;
            p = unpack2(ao1); ov[2] = p.x; ov[3] = p.y;
        }

        #pragma unroll
        for (int r = 0; r < 4; r++) {
            float si = fsigm(iv[r] + pg_i[r]);
            float sf = fsigm(fv[r] + pg_f[r]);
            float tg = ftanh(gv[r] + pg_g[r]);
            float so = fsigm(ov[r] + pg_o[r]);
            float c  = sf * creg[r] + si * tg;
            creg[r]  = c;
            float h  = so * ftanh(c);
            hout[rows[r] * HH + col] = h;
            if (writeHbuf)
                g_HBUF[((size_t)rows[r] * TT + t) * HH + col] = h;
        }

        // ---- mailbox grid barrier (contention-free) ----
        if (t < TT - 1) {
            __syncthreads();                       // all h stores issued
            if (tid == 0)
                st_release(&g_arrive[bid << 5], t + 1);   // own 128B line

            if (bid == 0 && tid < 32) {
                // aggregate: lane polls 4 distinct lines (MLP-4)
                const int f0 = (tid * 4 + 0) << 5;
                const int f1 = (tid * 4 + 1) << 5;
                const int f2 = (tid * 4 + 2) << 5;
                const int f3 = (tid * 4 + 3) << 5;
                const int need = t + 1;
                for (;;) {
                    int v0 = ld_acquire(&g_arrive[f0]);
                    int v1 = ld_acquire(&g_arrive[f1]);
                    int v2 = ld_acquire(&g_arrive[f2]);
                    int v3 = ld_acquire(&g_arrive[f3]);
                    if (v0 >= need && v1 >= need && v2 >= need && v3 >= need)
                        break;
                }
                __syncwarp();
                st_release(&g_release[f0], need);
                st_release(&g_release[f1], need);
                st_release(&g_release[f2], need);
                st_release(&g_release[f3], need);
            }

            // warm L2 with next step's pregates while peers arrive
            #pragma unroll
            for (int r = 0; r < 4; r++) {
                size_t base = ((size_t)rows[r] * TT + (t + 1)) * GG + col;
                asm volatile("prefetch.global.L2 [%0];" :: "l"(&g_GX[base]));
                asm volatile("prefetch.global.L2 [%0];" :: "l"(&g_GX[base + 256]));
                asm volatile("prefetch.global.L2 [%0];" :: "l"(&g_GX[base + 512]));
                asm volatile("prefetch.global.L2 [%0];" :: "l"(&g_GX[base + 768]));
            }

            if (tid == 0) {
                while (ld_acquire(&g_release[bid << 5]) < t + 1) { }
            }
            __syncthreads();
        }
    }
}

// ---------------- FC + log_softmax ------------------------------------------
__global__ void __launch_bounds__(128) fc_kernel(const float* __restrict__ wfc,
                                                 const float* __restrict__ bfc,
                                                 float* __restrict__ out) {
    const int b = blockIdx.x;
    const int tid = threadIdx.x;  // 128 = one class per thread
    __shared__ float h[256];
    // t = TT-1 = 511 (odd) -> final hout = g_H0
    h[tid] = g_H0[b * HH + tid];
    h[tid + 128] = g_H0[b * HH + tid + 128];
    __syncthreads();

    float acc = bfc[tid];
    const float* wp = wfc + (size_t)tid * HH;
    #pragma unroll 8
    for (int k = 0; k < 256; k++) acc += h[k] * wp[k];

    float m = acc;
    #pragma unroll
    for (int o = 16; o > 0; o >>= 1)
        m = fmaxf(m, __shfl_xor_sync(0xffffffffu, m, o));
    __shared__ float smax[4], ssum[4];
    int wid = tid >> 5, lane = tid & 31;
    if (lane == 0) smax[wid] = m;
    __syncthreads();
    m = fmaxf(fmaxf(smax[0], smax[1]), fmaxf(smax[2], smax[3]));

    float e = expf(acc - m);
    float s = e;
    #pragma unroll
    for (int o = 16; o > 0; o >>= 1)
        s += __shfl_xor_sync(0xffffffffu, s, o);
    if (lane == 0) ssum[wid] = s;
    __syncthreads();
    s = ssum[0] + ssum[1] + ssum[2] + ssum[3];

    out[b * CC + tid] = acc - m - logf(s);
}

// ---------------- launch ------------------------------------------------------
extern "C" void kernel_launch(void* const* d_in, const int* in_sizes, int n_in,
                              void* d_out, int out_size) {
    const float* x    = (const float*)d_in[0];
    const float* wih0 = (const float*)d_in[1];
    const float* whh0 = (const float*)d_in[2];
    const float* bih0 = (const float*)d_in[3];
    const float* bhh0 = (const float*)d_in[4];
    const float* wih1 = (const float*)d_in[5];
    const float* whh1 = (const float*)d_in[6];
    const float* bih1 = (const float*)d_in[7];
    const float* bhh1 = (const float*)d_in[8];
    const float* wfc  = (const float*)d_in[9];
    const float* bfc  = (const float*)d_in[10];
    float* out = (float*)d_out;

    const int persist_smem = (256 * 64 + 256 * 32) * (int)sizeof(float); // 96 KB
    cudaFuncSetAttribute(lstm_persist,
                         cudaFuncAttributeMaxDynamicSharedMemorySize,
                         persist_smem);

    dim3 gemm_grid(16, 1024);   // N/64, M/128

    // Layer 0
    gemm_gx<<<gemm_grid, 256>>>(x, 1, wih0, bih0, bhh0);
    reset_flags<<<8, 1024>>>();
    lstm_persist<<<128, 128, persist_smem>>>(whh0, 1);

    // Layer 1
    gemm_gx<<<gemm_grid, 256>>>(nullptr, 0, wih1, bih1, bhh1);
    reset_flags<<<8, 1024>>>();
    lstm_persist<<<128, 128, persist_smem>>>(whh1, 0);

    // Head
    fc_kernel<<<256, 128>>>(wfc, bfc, out);
}

// round 10
// speedup vs baseline: 1.6111x; 1.3314x over previous
#include <cuda_runtime.h>
#include <cuda_bf16.h>
#include <math.h>

typedef unsigned long long ull;

// Problem constants
#define BB   256          // batch
#define TT   512          // seq len
#define HH   256          // hidden
#define GG   1024         // 4*H gates
#define CC   128          // classes
#define MM   (BB*TT)      // 131072 rows for input GEMMs

// ---------------- scratch (device globals; no allocs allowed) ----------------
__device__ float g_GX[(size_t)MM * GG];      // 512 MB  pregates, layout [b][t][gate]
__device__ float g_HBUF[(size_t)MM * HH];    // 128 MB  layer-0 hidden states
__device__ float g_H0[BB * HH];
__device__ float g_H1[BB * HH];
__device__ unsigned int g_bar2[8 * 32];      // per-row-group barrier counters (128B apart)

// ---------------- packed f32x2 helpers (Blackwell FFMA2 path) ----------------
__device__ __forceinline__ ull pack2(float x, float y) {
    ull r;
    asm("mov.b64 %0, {%1, %2};" : "=l"(r) : "f"(x), "f"(y));
    return r;
}
__device__ __forceinline__ float2 unpack2(ull v) {
    float2 r;
    asm("mov.b64 {%0, %1}, %2;" : "=f"(r.x), "=f"(r.y) : "l"(v));
    return r;
}
__device__ __forceinline__ ull ffma2x(ull a, ull b, ull c) {
    ull d;
    asm("fma.rn.f32x2 %0, %1, %2, %3;" : "=l"(d) : "l"(a), "l"(b), "l"(c));
    return d;
}

// fast activations (error ~1e-6, well inside 1e-3 budget)
__device__ __forceinline__ float fsigm(float x) {
    float e = __expf(-x);
    return __fdividef(1.0f, 1.0f + e);
}
__device__ __forceinline__ float ftanh(float x) {
    float e = __expf(2.0f * x);           // overflow -> inf -> result 1 (correct)
    return 1.0f - __fdividef(2.0f, e + 1.0f);
}

__device__ __forceinline__ int ld_acquire_u(const unsigned int* p) {
    unsigned int v;
    asm volatile("ld.global.acquire.gpu.u32 %0, [%1];" : "=r"(v) : "l"(p) : "memory");
    return (int)v;
}

// ---------------- big GEMM:  Cout[m,n] = sum_k A[m,k]*W[n,k] + b1[n] + b2[n] --
// A: [MM,256] row-major (x, or g_HBUF), W: [1024,256] row-major.
// Tiles: BM=128, BN=64, BK=16, 256 threads, thread tile 8x4 (4 m-pairs x 4 n).
// Double-buffered smem: LDG of tile k+1 overlaps compute of tile k.
__global__ void __launch_bounds__(256) gemm_gx(const float* __restrict__ Aext,
                                               int useExt,
                                               const float* __restrict__ W,
                                               const float* __restrict__ b1,
                                               const float* __restrict__ b2) {
    __shared__ __align__(16) float As[2][16][128];
    __shared__ __align__(16) float Bs[2][16][64];

    const float* __restrict__ A = useExt ? Aext : g_HBUF;
    float* __restrict__ Cout = g_GX;

    const int tid = threadIdx.x;
    const int ty = tid >> 4;          // 0..15  (m group of 8)
    const int tx = tid & 15;          // 0..15  (n group of 4)
    const int bm0 = blockIdx.y * 128;
    const int bn0 = blockIdx.x * 64;

    const int a_row0 = tid >> 2;              // 0..63
    const int a_kg   = (tid & 3) * 4;
    const int b_row  = tid >> 2;
    const int b_kg   = (tid & 3) * 4;

    ull acc[4][4];
    #pragma unroll
    for (int i = 0; i < 4; i++)
        #pragma unroll
        for (int j = 0; j < 4; j++) acc[i][j] = 0ull;

    {
        #pragma unroll
        for (int i = 0; i < 2; i++) {
            int row = a_row0 + i * 64;
            float4 v = *(const float4*)&A[(size_t)(bm0 + row) * 256 + a_kg];
            As[0][a_kg + 0][row] = v.x; As[0][a_kg + 1][row] = v.y;
            As[0][a_kg + 2][row] = v.z; As[0][a_kg + 3][row] = v.w;
        }
        float4 v = *(const float4*)&W[(size_t)(bn0 + b_row) * 256 + b_kg];
        Bs[0][b_kg + 0][b_row] = v.x; Bs[0][b_kg + 1][b_row] = v.y;
        Bs[0][b_kg + 2][b_row] = v.z; Bs[0][b_kg + 3][b_row] = v.w;
    }
    __syncthreads();

    int buf = 0;
    for (int k0 = 0; k0 < 256; k0 += 16) {
        float4 pa0, pa1, pb;
        const bool more = (k0 + 16) < 256;
        if (more) {
            pa0 = *(const float4*)&A[(size_t)(bm0 + a_row0) * 256 + k0 + 16 + a_kg];
            pa1 = *(const float4*)&A[(size_t)(bm0 + a_row0 + 64) * 256 + k0 + 16 + a_kg];
            pb  = *(const float4*)&W[(size_t)(bn0 + b_row) * 256 + k0 + 16 + b_kg];
        }

        #pragma unroll
        for (int k = 0; k < 16; k++) {
            const ull* ap = (const ull*)&As[buf][k][ty * 8];
            ull a0 = ap[0], a1 = ap[1], a2 = ap[2], a3 = ap[3];
            float4 bv = *(const float4*)&Bs[buf][k][tx * 4];
            ull bb0 = pack2(bv.x, bv.x);
            ull bb1 = pack2(bv.y, bv.y);
            ull bb2 = pack2(bv.z, bv.z);
            ull bb3 = pack2(bv.w, bv.w);
            acc[0][0] = ffma2x(a0, bb0, acc[0][0]);
            acc[1][0] = ffma2x(a1, bb0, acc[1][0]);
            acc[2][0] = ffma2x(a2, bb0, acc[2][0]);
            acc[3][0] = ffma2x(a3, bb0, acc[3][0]);
            acc[0][1] = ffma2x(a0, bb1, acc[0][1]);
            acc[1][1] = ffma2x(a1, bb1, acc[1][1]);
            acc[2][1] = ffma2x(a2, bb1, acc[2][1]);
            acc[3][1] = ffma2x(a3, bb1, acc[3][1]);
            acc[0][2] = ffma2x(a0, bb2, acc[0][2]);
            acc[1][2] = ffma2x(a1, bb2, acc[1][2]);
            acc[2][2] = ffma2x(a2, bb2, acc[2][2]);
            acc[3][2] = ffma2x(a3, bb2, acc[3][2]);
            acc[0][3] = ffma2x(a0, bb3, acc[0][3]);
            acc[1][3] = ffma2x(a1, bb3, acc[1][3]);
            acc[2][3] = ffma2x(a2, bb3, acc[2][3]);
            acc[3][3] = ffma2x(a3, bb3, acc[3][3]);
        }

        if (more) {
            int nb = buf ^ 1;
            As[nb][a_kg + 0][a_row0] = pa0.x; As[nb][a_kg + 1][a_row0] = pa0.y;
            As[nb][a_kg + 2][a_row0] = pa0.z; As[nb][a_kg + 3][a_row0] = pa0.w;
            As[nb][a_kg + 0][a_row0 + 64] = pa1.x; As[nb][a_kg + 1][a_row0 + 64] = pa1.y;
            As[nb][a_kg + 2][a_row0 + 64] = pa1.z; As[nb][a_kg + 3][a_row0 + 64] = pa1.w;
            Bs[nb][b_kg + 0][b_row] = pb.x; Bs[nb][b_kg + 1][b_row] = pb.y;
            Bs[nb][b_kg + 2][b_row] = pb.z; Bs[nb][b_kg + 3][b_row] = pb.w;
            __syncthreads();
            buf = nb;
        }
    }

    float4 b1v = *(const float4*)&b1[bn0 + tx * 4];
    float4 b2v = *(const float4*)&b2[bn0 + tx * 4];
    float4 bias = make_float4(b1v.x + b2v.x, b1v.y + b2v.y,
                              b1v.z + b2v.z, b1v.w + b2v.w);
    #pragma unroll
    for (int i = 0; i < 4; i++) {
        float2 q0 = unpack2(acc[i][0]);
        float2 q1 = unpack2(acc[i][1]);
        float2 q2 = unpack2(acc[i][2]);
        float2 q3 = unpack2(acc[i][3]);
        size_t r0 = (size_t)(bm0 + ty * 8 + 2 * i);
        float4 v0 = make_float4(q0.x + bias.x, q1.x + bias.y, q2.x + bias.z, q3.x + bias.w);
        float4 v1 = make_float4(q0.y + bias.x, q1.y + bias.y, q2.y + bias.z, q3.y + bias.w);
        *(float4*)&Cout[r0 * GG + bn0 + tx * 4] = v0;
        *(float4*)&Cout[(r0 + 1) * GG + bn0 + tx * 4] = v1;
    }
}

// ---------------- barrier reset ----------------
__global__ void reset_bar2() {
    int i = threadIdx.x;
    if (i < 8 * 32) g_bar2[i] = 0u;
}

// ---------------- persistent recurrence kernel -------------------------------
// 128 CTAs x 128 threads (best-measured config). CTA = 32 batch rows x 16
// h-cols (x4 gates). Thread = 4 rows x 1 col, accumulating gate-pairs
// (i,f),(g,o) per row as f32x2 -> zero weight packs in the k-loop.
// h staged ROW-MAJOR in smem with float4 stores (4 STS.128/thread, was 64
// scalar STS). Weights (64KB) staged once. Barrier: per-row-group counters
// (16 CTAs each) -> 8x less contention; pregates prefetched into registers
// during the barrier window.
__global__ void __launch_bounds__(128, 1) lstm_persist(const float* __restrict__ whh,
                                                       int writeHbuf) {
    extern __shared__ float sm[];
    float* sWs = sm;                 // [256][64]  sWs[k*64 + hcol*4 + gate]
    float* sAs = sm + 256 * 64;      // [32][260]  h row-major, padded stride

    const int tid  = threadIdx.x;
    const int bid  = blockIdx.x;
    const int hcol = tid & 15;
    const int rq   = tid >> 4;               // 0..7
    const int c0   = (bid & 15) * 16;        // h-col group
    const int grp  = bid >> 4;               // row group 0..7
    const int bm   = grp * 32;               // batch rows
    const int col  = c0 + hcol;

    // one-time weight stage: 64 gate-rows (hcol*4+g) x 256 k
    for (int i = tid; i < 64 * 64; i += 128) {
        int lr = i >> 6;              // 0..63 local row
        int kk = (i & 63) * 4;        // k0
        int bh = lr >> 2, g = lr & 3;
        float4 v = *(const float4*)&whh[(size_t)(g * HH + c0 + bh) * HH + kk];
        sWs[(kk + 0) * 64 + lr] = v.x;
        sWs[(kk + 1) * 64 + lr] = v.y;
        sWs[(kk + 2) * 64 + lr] = v.z;
        sWs[(kk + 3) * 64 + lr] = v.w;
    }
    __syncthreads();

    float creg[4] = {0.f, 0.f, 0.f, 0.f};
    int rows[4];
    #pragma unroll
    for (int r = 0; r < 4; r++) rows[r] = bm + rq * 4 + r;

    // t=0 pregate prefetch (GX layout [b][t][gate])
    float pg_i[4], pg_f[4], pg_g[4], pg_o[4];
    #pragma unroll
    for (int r = 0; r < 4; r++) {
        size_t base = (size_t)rows[r] * TT * GG + col;   // t=0
        pg_i[r] = g_GX[base];
        pg_f[r] = g_GX[base + 256];
        pg_g[r] = g_GX[base + 512];
        pg_o[r] = g_GX[base + 768];
    }

    const int sr  = tid & 31;          // staging row 0..31
    const int skc = tid >> 5;          // staging k-chunk 0..3 (64 k each)

    unsigned int* barp = &g_bar2[grp * 32];

    for (int t = 0; t < TT; t++) {
        const float* __restrict__ hin  = (t & 1) ? g_H1 : g_H0;
        float* __restrict__       hout = (t & 1) ? g_H0 : g_H1;

        ull aif[4] = {0, 0, 0, 0};
        ull ago[4] = {0, 0, 0, 0};

        if (t > 0) {   // h == 0 at t=0, recurrent term vanishes
            // stage hin (32 rows x 256 k) row-major, vectorized
            {
                const float* hrow = &hin[(bm + sr) * HH + skc * 64];
                float* dst = &sAs[sr * 260 + skc * 64];
                #pragma unroll
                for (int j = 0; j < 16; j++)
                    *(float4*)&dst[j * 4] = *(const float4*)&hrow[j * 4];
            }
            __syncthreads();

            const float* hr0 = &sAs[(rq * 4 + 0) * 260];
            const float* hr1 = &sAs[(rq * 4 + 1) * 260];
            const float* hr2 = &sAs[(rq * 4 + 2) * 260];
            const float* hr3 = &sAs[(rq * 4 + 3) * 260];
            const float* bp  = &sWs[hcol * 4];

            #pragma unroll 4
            for (int k4 = 0; k4 < 256; k4 += 4) {
                float hv0[4], hv1[4], hv2[4], hv3[4];
                *(float4*)hv0 = *(const float4*)&hr0[k4];
                *(float4*)hv1 = *(const float4*)&hr1[k4];
                *(float4*)hv2 = *(const float4*)&hr2[k4];
                *(float4*)hv3 = *(const float4*)&hr3[k4];
                #pragma unroll
                for (int j = 0; j < 4; j++) {
                    ulonglong2 wv = *(const ulonglong2*)(bp + (k4 + j) * 64);
                    ull a0 = pack2(hv0[j], hv0[j]);
                    ull a1 = pack2(hv1[j], hv1[j]);
                    ull a2 = pack2(hv2[j], hv2[j]);
                    ull a3 = pack2(hv3[j], hv3[j]);
                    aif[0] = ffma2x(a0, wv.x, aif[0]);
                    ago[0] = ffma2x(a0, wv.y, ago[0]);
                    aif[1] = ffma2x(a1, wv.x, aif[1]);
                    ago[1] = ffma2x(a1, wv.y, ago[1]);
                    aif[2] = ffma2x(a2, wv.x, aif[2]);
                    ago[2] = ffma2x(a2, wv.y, ago[2]);
                    aif[3] = ffma2x(a3, wv.x, aif[3]);
                    ago[3] = ffma2x(a3, wv.y, ago[3]);
                }
            }
            __syncthreads();   // sAs re-staged next step
        }

        #pragma unroll
        for (int r = 0; r < 4; r++) {
            float2 fif = unpack2(aif[r]);
            float2 fgo = unpack2(ago[r]);
            float si = fsigm(fif.x + pg_i[r]);
            float sf = fsigm(fif.y + pg_f[r]);
            float tg = ftanh(fgo.x + pg_g[r]);
            float so = fsigm(fgo.y + pg_o[r]);
            float c  = sf * creg[r] + si * tg;
            creg[r]  = c;
            float h  = so * ftanh(c);
            hout[rows[r] * HH + col] = h;
            if (writeHbuf)
                g_HBUF[((size_t)rows[r] * TT + t) * HH + col] = h;
        }

        // ---- per-row-group barrier (16 CTAs per counter) ----
        if (t < TT - 1) {
            __syncthreads();                       // all h stores issued
            if (tid == 0) {
                __threadfence();                   // release h to GPU scope
                atomicAdd(barp, 1u);
            }
            // prefetch next step's pregates into registers while peers arrive
            #pragma unroll
            for (int r = 0; r < 4; r++) {
                size_t base = ((size_t)rows[r] * TT + (t + 1)) * GG + col;
                pg_i[r] = g_GX[base];
                pg_f[r] = g_GX[base + 256];
                pg_g[r] = g_GX[base + 512];
                pg_o[r] = g_GX[base + 768];
            }
            if (tid == 0) {
                int target = (t + 1) * 16;
                while (ld_acquire_u(barp) < target) { }
            }
            __syncthreads();
        }
    }
}

// ---------------- FC + log_softmax ------------------------------------------
__global__ void __launch_bounds__(128) fc_kernel(const float* __restrict__ wfc,
                                                 const float* __restrict__ bfc,
                                                 float* __restrict__ out) {
    const int b = blockIdx.x;
    const int tid = threadIdx.x;  // 128 = one class per thread
    __shared__ float h[256];
    // t = TT-1 = 511 (odd) -> final hout = g_H0
    h[tid] = g_H0[b * HH + tid];
    h[tid + 128] = g_H0[b * HH + tid + 128];
    __syncthreads();

    float acc = bfc[tid];
    const float* wp = wfc + (size_t)tid * HH;
    #pragma unroll 8
    for (int k = 0; k < 256; k++) acc += h[k] * wp[k];

    float m = acc;
    #pragma unroll
    for (int o = 16; o > 0; o >>= 1)
        m = fmaxf(m, __shfl_xor_sync(0xffffffffu, m, o));
    __shared__ float smax[4], ssum[4];
    int wid = tid >> 5, lane = tid & 31;
    if (lane == 0) smax[wid] = m;
    __syncthreads();
    m = fmaxf(fmaxf(smax[0], smax[1]), fmaxf(smax[2], smax[3]));

    float e = expf(acc - m);
    float s = e;
    #pragma unroll
    for (int o = 16; o > 0; o >>= 1)
        s += __shfl_xor_sync(0xffffffffu, s, o);
    if (lane == 0) ssum[wid] = s;
    __syncthreads();
    s = ssum[0] + ssum[1] + ssum[2] + ssum[3];

    out[b * CC + tid] = acc - m - logf(s);
}

// ---------------- launch ------------------------------------------------------
extern "C" void kernel_launch(void* const* d_in, const int* in_sizes, int n_in,
                              void* d_out, int out_size) {
    const float* x    = (const float*)d_in[0];
    const float* wih0 = (const float*)d_in[1];
    const float* whh0 = (const float*)d_in[2];
    const float* bih0 = (const float*)d_in[3];
    const float* bhh0 = (const float*)d_in[4];
    const float* wih1 = (const float*)d_in[5];
    const float* whh1 = (const float*)d_in[6];
    const float* bih1 = (const float*)d_in[7];
    const float* bhh1 = (const float*)d_in[8];
    const float* wfc  = (const float*)d_in[9];
    const float* bfc  = (const float*)d_in[10];
    float* out = (float*)d_out;

    const int persist_smem = (256 * 64 + 32 * 260) * (int)sizeof(float); // ~98.6 KB
    cudaFuncSetAttribute(lstm_persist,
                         cudaFuncAttributeMaxDynamicSharedMemorySize,
                         persist_smem);

    dim3 gemm_grid(16, 1024);   // N/64, M/128

    // Layer 0
    gemm_gx<<<gemm_grid, 256>>>(x, 1, wih0, bih0, bhh0);
    reset_bar2<<<1, 256>>>();
    lstm_persist<<<128, 128, persist_smem>>>(whh0, 1);

    // Layer 1
    gemm_gx<<<gemm_grid, 256>>>(nullptr, 0, wih1, bih1, bhh1);
    reset_bar2<<<1, 256>>>();
    lstm_persist<<<128, 128, persist_smem>>>(whh1, 0);

    // Head
    fc_kernel<<<256, 128>>>(wfc, bfc, out);
}